// round 6
// baseline (speedup 1.0000x reference)
#include <cuda_runtime.h>

// ---------------------------------------------------------------------------
// Fused: channel-mix (64->16) -> double-unfold 3x3 along W (masked) ->
//        group conv mix (8g x 9taps -> 32) -> roll(+1,H) -> NCHW out.
//
// grid=256: each CTA does one h-half (7 rows) of one batch image -> smem
// 83.4KB -> 2 CTAs/SM (32 warps) for latency hiding. The unfold is W-only,
// so h-halves are fully independent.
// Stage 1 writes T4 transposed (p-major rows of 18 wd floats) to smem.
// Stage 2: lane=(p,jg), w-packed f32x2 accumulators; weights pre-dup-packed
// (w,w) ulls in smem; rank-1 edge corrections at w=0/w=13.
// ---------------------------------------------------------------------------

typedef unsigned long long ull;

#define ROWBLK 290                    // floats per (g,hl) block: 16*18 + 2 pad
#define NH     7                      // h rows per CTA
#define T4N    (8*NH*ROWBLK)          // 16240 floats
#define WEFFD_N (8*5*32)              // dup-packed weights (ull)
#define WMIXN  1024                   // 64*16 floats
#define CORRN  (8*32)                 // ulls per correction table
#define SMEM_BYTES (T4N*4 + WEFFD_N*8 + WMIXN*4 + CORRN*8*2)   // 83392

__device__ __forceinline__ ull pack2(float lo, float hi){
    ull r; asm("mov.b64 %0, {%1, %2};" : "=l"(r) : "f"(lo), "f"(hi)); return r;
}
__device__ __forceinline__ void unpack2(ull v, float &lo, float &hi){
    asm("mov.b64 {%0, %1}, %2;" : "=f"(lo), "=f"(hi) : "l"(v));
}
__device__ __forceinline__ void ffma2(ull &d, ull a, ull b){
    asm("fma.rn.f32x2 %0, %1, %2, %0;" : "+l"(d) : "l"(a), "l"(b));
}

__global__ void __launch_bounds__(512, 2)
fused_mix_unfold_conv(const float* __restrict__ x,
                      const float* __restrict__ wconv,
                      const float* __restrict__ wmix,
                      float* __restrict__ out)
{
    extern __shared__ float smem[];
    float* t4s     = smem;                       // [g][hl] blocks of ROWBLK
    ull*   weffd   = (ull*)(smem + T4N);         // [g][d][j] packed (w,w)
    float* wmixs   = (float*)(weffd + WEFFD_N);  // [j64][p16]
    ull*   corr0d  = (ull*)(wmixs + WMIXN);      // [g][j]  (-c, 0)
    ull*   corr13d = corr0d + CORRN;             // [g][j]  (0, -c)

    const int tid  = threadIdx.x;
    const int b    = blockIdx.x >> 1;
    const int h0   = (blockIdx.x & 1) * NH;      // 0 or 7

    // ---------------- prologue: wmix copy, T4 pad-zero, Weff, corrections --
    for (int i = tid; i < WMIXN; i += 512) wmixs[i] = wmix[i];

    // zero pad wd rows {0,1,16,17} for all (g,hl,p)
    for (int i = tid; i < 8*NH*16*4; i += 512) {
        int blk = i >> 6, r = i & 63;
        int p = r >> 2, wi = r & 3;
        int wd = (wi < 2) ? wi : (wi + 14);
        t4s[blk*ROWBLK + p*18 + wd] = 0.f;
    }

    // interior dup-packed Weff[g][d][j] = (a,a), a = sum_kb wconv[g][kb][d-kb][j]
    for (int e = tid; e < WEFFD_N; e += 512) {
        int j = e & 31;
        int d = (e >> 5) % 5;
        int g = e / 160;
        float a = 0.f;
        #pragma unroll
        for (int kb = 0; kb < 3; ++kb) {
            int ka = d - kb;
            if (ka >= 0 && ka <= 2)
                a += wconv[((g*3 + kb)*3 + ka)*32 + j];
        }
        weffd[e] = pack2(a, a);
    }

    // corrections: w=0 drops the kb=0 tap (ka=2):  c0  = wconv[g][0][2][j]
    //              w=13 drops the kb=2 tap (ka=0): c13 = wconv[g][2][0][j]
    for (int e = tid; e < CORRN; e += 512) {
        int j = e & 31, g = e >> 5;
        corr0d [e] = pack2(-wconv[((g*3 + 0)*3 + 2)*32 + j], 0.f);
        corr13d[e] = pack2(0.f, -wconv[((g*3 + 2)*3 + 0)*32 + j]);
    }
    __syncthreads();

    // ---------------- stage 1: T4[g,hl,w,p] = sum_j x[b,j,g,h0+hl,w]*wmix[j,p]
    if (tid < 392) {
        int s0 = tid * 2;                    // 2 points/thread, same g chunk
        int g  = s0 / 98, rem = s0 % 98;     // rem even -> float2 aligned
        const float* xb = x + (size_t)b * 100352 + g*196 + h0*14 + rem;

        ull acc[2][8];
        #pragma unroll
        for (int pt = 0; pt < 2; ++pt)
            #pragma unroll
            for (int pp = 0; pp < 8; ++pp) acc[pt][pp] = 0ull;

        #pragma unroll 8
        for (int j = 0; j < 64; ++j) {
            float2 xv = *(const float2*)(xb + j * 1568);
            const ulonglong2* wrow = (const ulonglong2*)(wmixs + j * 16);
            ulonglong2 w01 = wrow[0], w23 = wrow[1], w45 = wrow[2], w67 = wrow[3];
            ull wp[8] = {w01.x, w01.y, w23.x, w23.y, w45.x, w45.y, w67.x, w67.y};
            ull x0 = pack2(xv.x, xv.x), x1 = pack2(xv.y, xv.y);
            #pragma unroll
            for (int pp = 0; pp < 8; ++pp) {
                ffma2(acc[0][pp], x0, wp[pp]);
                ffma2(acc[1][pp], x1, wp[pp]);
            }
        }
        #pragma unroll
        for (int pt = 0; pt < 2; ++pt) {
            int rp = rem + pt;
            int hl = rp / 14, w = rp % 14;
            float* dst = t4s + (g*NH + hl)*ROWBLK + (w + 2);
            float v[16];
            #pragma unroll
            for (int q = 0; q < 8; ++q) unpack2(acc[pt][q], v[2*q], v[2*q+1]);
            #pragma unroll
            for (int p = 0; p < 16; ++p) dst[p*18] = v[p];
        }
    }
    __syncthreads();

    // ---------------- stage 2 ---------------------------------------------
    const int lid = tid & 31;
    const int wid = tid >> 5;
    const int p   = lid & 15;
    const int jg  = lid >> 4;               // 0..1

    const size_t obase = (size_t)b * 100352;

    #pragma unroll 1
    for (int it = 0; it < 2; ++it) {
        int task = wid + 16*it;             // 28 tasks, SMSP-balanced (7 each)
        if (task >= 28) continue;
        int jq = task & 3;
        int hl = task >> 2;
        int jb = jq*8 + jg*4;               // this thread's 4 j's: jb..jb+3

        ull a0[7], a1[7], a2[7], a3[7];
        #pragma unroll
        for (int k = 0; k < 7; ++k) { a0[k]=0; a1[k]=0; a2[k]=0; a3[k]=0; }

        #pragma unroll 1
        for (int g = 0; g < 8; ++g) {
            const float2* row = (const float2*)(t4s + (g*NH + hl)*ROWBLK + p*18);
            float2 f[9];
            #pragma unroll
            for (int k = 0; k < 9; ++k) f[k] = row[k];

            ull E[9], O[8];
            #pragma unroll
            for (int k = 0; k < 9; ++k) E[k] = pack2(f[k].x, f[k].y);
            #pragma unroll
            for (int k = 0; k < 8; ++k) O[k] = pack2(f[k].y, f[k+1].x);

            const ull* wg = weffd + g*160 + jb;
            #pragma unroll
            for (int d = 0; d < 5; ++d) {
                ulonglong2 wA = *(const ulonglong2*)(wg + d*32);
                ulonglong2 wB = *(const ulonglong2*)(wg + d*32 + 2);
                #pragma unroll
                for (int wp = 0; wp < 7; ++wp) {
                    ull t = (d & 1) ? O[((d-1)>>1) + wp] : E[(d>>1) + wp];
                    ffma2(a0[wp], t, wA.x);
                    ffma2(a1[wp], t, wA.y);
                    ffma2(a2[wp], t, wB.x);
                    ffma2(a3[wp], t, wB.y);
                }
            }

            // edge corrections: w=0 uses t4 idx2 (f[1].x), lo half of acc[0]
            //                   w=13 uses idx15 (f[7].y), hi half of acc[6]
            {
                const ulonglong2* c0 = (const ulonglong2*)(corr0d  + g*32 + jb);
                const ulonglong2* c3 = (const ulonglong2*)(corr13d + g*32 + jb);
                ulonglong2 c0a = c0[0], c0b = c0[1];
                ulonglong2 c3a = c3[0], c3b = c3[1];
                ull m2  = E[1];                      // (f1.x, f1.y); lo used
                ull m15 = pack2(f[7].y, f[7].y);
                ffma2(a0[0], m2, c0a.x);  ffma2(a1[0], m2, c0a.y);
                ffma2(a2[0], m2, c0b.x);  ffma2(a3[0], m2, c0b.y);
                ffma2(a0[6], m15, c3a.x); ffma2(a1[6], m15, c3a.y);
                ffma2(a2[6], m15, c3b.x); ffma2(a3[6], m15, c3b.y);
            }
        }

        int h_o = h0 + hl + 1; if (h_o == 14) h_o = 0;   // roll(+1, H)

        #pragma unroll
        for (int jj = 0; jj < 4; ++jj) {
            ull* a = (jj==0) ? a0 : (jj==1) ? a1 : (jj==2) ? a2 : a3;
            int ch = (jb + jj)*16 + p;
            float* ob = out + obase + (size_t)ch*196 + h_o*14;
            if ((h_o & 1) == 0) {
                ((ulonglong2*)ob)[0]     = make_ulonglong2(a[0], a[1]);
                ((ulonglong2*)(ob+4))[0] = make_ulonglong2(a[2], a[3]);
                ((ulonglong2*)(ob+8))[0] = make_ulonglong2(a[4], a[5]);
                *(ull*)(ob+12) = a[6];
            } else {
                *(ull*)ob = a[0];
                ((ulonglong2*)(ob+2))[0]  = make_ulonglong2(a[1], a[2]);
                ((ulonglong2*)(ob+6))[0]  = make_ulonglong2(a[3], a[4]);
                ((ulonglong2*)(ob+10))[0] = make_ulonglong2(a[5], a[6]);
            }
        }
    }
}

extern "C" void kernel_launch(void* const* d_in, const int* in_sizes, int n_in,
                              void* d_out, int out_size) {
    const float* x     = (const float*)d_in[0];
    const float* wconv = (const float*)d_in[1];
    const float* wmix  = (const float*)d_in[2];
    float* out = (float*)d_out;
    (void)in_sizes; (void)n_in; (void)out_size;

    cudaFuncSetAttribute(fused_mix_unfold_conv,
                         cudaFuncAttributeMaxDynamicSharedMemorySize,
                         SMEM_BYTES);
    fused_mix_unfold_conv<<<256, 512, SMEM_BYTES>>>(x, wconv, wmix, out);
}

// round 7
// speedup vs baseline: 3.7936x; 3.7936x over previous
#include <cuda_runtime.h>

// ---------------------------------------------------------------------------
// Fused: channel-mix (64->16) -> double-unfold 3x3 along W (masked) ->
//        group conv mix (8g x 9taps -> 32) -> roll(+1,H) -> NCHW out.
//
// One CTA per batch image (grid=128, 512 threads, 128 regs).
// Stage 1: T4 transposed to smem, p-major rows of 20 floats (16B aligned).
// Stage 2: even/odd packed-accumulator split (A: even taps, B: odd taps),
//          both consuming aligned E-pairs directly -> near-zero MOV packs.
//          Weights pre-dup-packed (w,w) ulls in smem. Rank-1 edge
//          corrections at w=0/w=13 fold onto E[1]/E[7].
// ---------------------------------------------------------------------------

typedef unsigned long long ull;

#define ROWP   20                     // floats per p-row (80B, 16B aligned)
#define ROWBLK (16*ROWP)              // 320 floats per (g,h) block
#define T4N    (8*14*ROWBLK)          // 35840 floats
#define WEFFD_N (8*5*32)              // dup-packed weights (ull)
#define WMIXN  1024                   // 64*16 floats
#define CORRN  (8*32)                 // ulls per correction table
#define SMEM_BYTES (T4N*4 + WEFFD_N*8 + WMIXN*4 + CORRN*8*2)   // 161792

__device__ __forceinline__ ull pack2(float lo, float hi){
    ull r; asm("mov.b64 %0, {%1, %2};" : "=l"(r) : "f"(lo), "f"(hi)); return r;
}
__device__ __forceinline__ void unpack2(ull v, float &lo, float &hi){
    asm("mov.b64 {%0, %1}, %2;" : "=f"(lo), "=f"(hi) : "l"(v));
}
__device__ __forceinline__ void ffma2(ull &d, ull a, ull b){
    asm("fma.rn.f32x2 %0, %1, %2, %0;" : "+l"(d) : "l"(a), "l"(b));
}

__global__ void __launch_bounds__(512, 1)
fused_mix_unfold_conv(const float* __restrict__ x,
                      const float* __restrict__ wconv,
                      const float* __restrict__ wmix,
                      float* __restrict__ out)
{
    extern __shared__ float smem[];
    float* t4s     = smem;                       // [g][h] blocks of ROWBLK
    ull*   weffd   = (ull*)(smem + T4N);         // [g][d][j] packed (w,w)
    float* wmixs   = (float*)(weffd + WEFFD_N);  // [j64][p16]
    ull*   corr0d  = (ull*)(wmixs + WMIXN);      // [g][j]  (-c0, 0)
    ull*   corr13d = corr0d + CORRN;             // [g][j]  (0, -c13)

    const int tid = threadIdx.x;
    const int b   = blockIdx.x;

    // ---------------- prologue --------------------------------------------
    for (int i = tid; i < WMIXN; i += 512) wmixs[i] = wmix[i];

    // zero pad wd slots {0,1,16,17} for all (g,h,p)
    for (int i = tid; i < 8*14*16*4; i += 512) {
        int blk = i >> 6, r = i & 63;
        int p = r >> 2, wi = r & 3;
        int wd = (wi < 2) ? wi : (wi + 14);
        t4s[blk*ROWBLK + p*ROWP + wd] = 0.f;
    }

    // interior dup-packed Weff[g][d][j] = (a,a), a = sum_kb wconv[g][kb][d-kb][j]
    for (int e = tid; e < WEFFD_N; e += 512) {
        int j = e & 31;
        int d = (e >> 5) % 5;
        int g = e / 160;
        float a = 0.f;
        #pragma unroll
        for (int kb = 0; kb < 3; ++kb) {
            int ka = d - kb;
            if (ka >= 0 && ka <= 2)
                a += wconv[((g*3 + kb)*3 + ka)*32 + j];
        }
        weffd[e] = pack2(a, a);
    }

    // corrections: w=0 loses kb=0 tap (only d=2 nonzero): c0 = wconv[g][0][2][j],
    //              multiplies t[0] = lo(E[1]).
    //              w=13 loses kb=2 tap (d=2): c13 = wconv[g][2][0][j],
    //              multiplies t[13] = hi(E[7]).
    for (int e = tid; e < CORRN; e += 512) {
        int j = e & 31, g = e >> 5;
        corr0d [e] = pack2(-wconv[((g*3 + 0)*3 + 2)*32 + j], 0.f);
        corr13d[e] = pack2(0.f, -wconv[((g*3 + 2)*3 + 0)*32 + j]);
    }
    __syncthreads();

    // ---------------- stage 1: T4[g,h,w,p] = sum_j x[b,j,s] * wmix[j,p] ----
    if (tid < 392) {
        const float* xb = x + (size_t)b * 100352 + tid * 4;
        ull acc[4][8];
        #pragma unroll
        for (int pt = 0; pt < 4; ++pt)
            #pragma unroll
            for (int pp = 0; pp < 8; ++pp) acc[pt][pp] = 0ull;

        #pragma unroll 8
        for (int j = 0; j < 64; ++j) {
            float4 xv = *(const float4*)(xb + j * 1568);
            const ulonglong2* wrow = (const ulonglong2*)(wmixs + j * 16);
            ulonglong2 w01 = wrow[0], w23 = wrow[1], w45 = wrow[2], w67 = wrow[3];
            ull wp[8] = {w01.x, w01.y, w23.x, w23.y, w45.x, w45.y, w67.x, w67.y};
            ull xbc[4] = {pack2(xv.x, xv.x), pack2(xv.y, xv.y),
                          pack2(xv.z, xv.z), pack2(xv.w, xv.w)};
            #pragma unroll
            for (int pt = 0; pt < 4; ++pt)
                #pragma unroll
                for (int pp = 0; pp < 8; ++pp)
                    ffma2(acc[pt][pp], xbc[pt], wp[pp]);
        }
        #pragma unroll
        for (int pt = 0; pt < 4; ++pt) {
            int s = tid * 4 + pt;
            int g = s / 196, rem = s % 196;
            int h = rem / 14, w = rem % 14;
            float* dst = t4s + (g*14 + h)*ROWBLK + (w + 2);
            float v[16];
            #pragma unroll
            for (int q = 0; q < 8; ++q) unpack2(acc[pt][q], v[2*q], v[2*q+1]);
            #pragma unroll
            for (int p = 0; p < 16; ++p) dst[p*ROWP] = v[p];
        }
    }
    __syncthreads();

    // ---------------- stage 2 ---------------------------------------------
    const int lid = tid & 31;
    const int wid = tid >> 5;
    const int p   = lid & 15;
    const int jg  = lid >> 4;               // 0..1

    const size_t obase = (size_t)b * 100352;

    #pragma unroll 1
    for (int it = 0; it < 7; ++it) {
        int task = wid + 16*it;             // 112 tasks, 7/warp, SMSP-balanced
        int jq = task & 7;
        int h  = task >> 3;
        int jb = jq*4 + jg*2;               // this thread's 2 j's: jb, jb+1

        // A[i] = (out[2i], out[2i+1]) : even taps d=0,2,4 + corrections
        // B[i] = (out[2i-1], out[2i]) : odd taps d=1,3 (pads absorb edges)
        ull A0[7], A1[7], B0[8], B1[8];
        #pragma unroll
        for (int k = 0; k < 7; ++k) { A0[k]=0; A1[k]=0; }
        #pragma unroll
        for (int k = 0; k < 8; ++k) { B0[k]=0; B1[k]=0; }

        #pragma unroll 1
        for (int g = 0; g < 8; ++g) {
            const ull* row = (const ull*)(t4s + (g*14 + h)*ROWBLK + p*ROWP);
            ull E[9];
            #pragma unroll
            for (int k = 0; k < 9; ++k) E[k] = row[k];

            const ull* wg = weffd + g*160 + jb;
            ulonglong2 w0 = *(const ulonglong2*)(wg);        // d=0
            ulonglong2 w1 = *(const ulonglong2*)(wg + 32);   // d=1
            ulonglong2 w2 = *(const ulonglong2*)(wg + 64);   // d=2
            ulonglong2 w3 = *(const ulonglong2*)(wg + 96);   // d=3
            ulonglong2 w4 = *(const ulonglong2*)(wg + 128);  // d=4

            #pragma unroll
            for (int i = 0; i < 7; ++i) {
                ffma2(A0[i], E[i],   w0.x);  ffma2(A1[i], E[i],   w0.y);
                ffma2(A0[i], E[i+1], w2.x);  ffma2(A1[i], E[i+1], w2.y);
                ffma2(A0[i], E[i+2], w4.x);  ffma2(A1[i], E[i+2], w4.y);
            }
            #pragma unroll
            for (int i = 0; i < 8; ++i) {
                ffma2(B0[i], E[i],   w1.x);  ffma2(B1[i], E[i],   w1.y);
                ffma2(B0[i], E[i+1], w3.x);  ffma2(B1[i], E[i+1], w3.y);
            }

            // edge corrections (even-tap family -> into A)
            ulonglong2 c0 = *(const ulonglong2*)(corr0d  + g*32 + jb);
            ulonglong2 c3 = *(const ulonglong2*)(corr13d + g*32 + jb);
            ffma2(A0[0], E[1], c0.x);  ffma2(A1[0], E[1], c0.y);
            ffma2(A0[6], E[7], c3.x);  ffma2(A1[6], E[7], c3.y);
        }

        int h_o = h + 1; if (h_o == 14) h_o = 0;   // roll(+1, H)

        #pragma unroll
        for (int jj = 0; jj < 2; ++jj) {
            ull* A = jj ? A1 : A0;
            ull* B = jj ? B1 : B0;
            float o[14];
            #pragma unroll
            for (int i = 0; i < 7; ++i) {
                float al, ah, bl0, bh0, bl1, bh1;
                unpack2(A[i],   al,  ah);
                unpack2(B[i],   bl0, bh0);
                unpack2(B[i+1], bl1, bh1);
                o[2*i]   = al + bh0;
                o[2*i+1] = ah + bl1;
            }
            int ch = (jb + jj)*16 + p;
            float* ob = out + obase + (size_t)ch*196 + h_o*14;
            if ((h_o & 1) == 0) {               // 16B aligned
                *(float4*)(ob)      = make_float4(o[0], o[1], o[2], o[3]);
                *(float4*)(ob + 4)  = make_float4(o[4], o[5], o[6], o[7]);
                *(float4*)(ob + 8)  = make_float4(o[8], o[9], o[10], o[11]);
                *(float2*)(ob + 12) = make_float2(o[12], o[13]);
            } else {                            // 8B aligned
                *(float2*)(ob)      = make_float2(o[0], o[1]);
                *(float4*)(ob + 2)  = make_float4(o[2], o[3], o[4], o[5]);
                *(float4*)(ob + 6)  = make_float4(o[6], o[7], o[8], o[9]);
                *(float4*)(ob + 10) = make_float4(o[10], o[11], o[12], o[13]);
            }
        }
    }
}

extern "C" void kernel_launch(void* const* d_in, const int* in_sizes, int n_in,
                              void* d_out, int out_size) {
    const float* x     = (const float*)d_in[0];
    const float* wconv = (const float*)d_in[1];
    const float* wmix  = (const float*)d_in[2];
    float* out = (float*)d_out;
    (void)in_sizes; (void)n_in; (void)out_size;

    cudaFuncSetAttribute(fused_mix_unfold_conv,
                         cudaFuncAttributeMaxDynamicSharedMemorySize,
                         SMEM_BYTES);
    fused_mix_unfold_conv<<<128, 512, SMEM_BYTES>>>(x, wconv, wmix, out);
}